// round 1
// baseline (speedup 1.0000x reference)
#include <cuda_runtime.h>
#include <cuda_bf16.h>

// Problem constants
#define BB   2
#define TT   2048
#define CC   1024
#define HH   16
#define DD   64
#define MM   (BB*TT)        // 4096
#define NQKV (3*CC)         // 3072

// Scratch (device globals: allocation-free rule)
__device__ float g_Q[(size_t)BB*HH*TT*DD];   // [B,H,T,64]
__device__ float g_K[(size_t)BB*HH*TT*DD];
__device__ float g_V[(size_t)BB*HH*TT*DD];
__device__ float g_Y[(size_t)MM*CC];         // [B,T,C] attention output

// ---------------------------------------------------------------------------
// Tiled fp32 GEMM: C[M,N] = A[M,K] @ B[K,N]
// BM=128, BN=64, BK=16, 256 threads, 8x4 microtile per thread.
// MODE 1: QKV gemm — scatter into g_Q/g_K/g_V ([B,H,T,64])
// MODE 2: proj gemm — A is g_Y, store直接 to Cout
// ---------------------------------------------------------------------------
template <int MODE>
__global__ __launch_bounds__(256) void gemm_kernel(const float* __restrict__ A,
                                                   const float* __restrict__ Bm,
                                                   float* __restrict__ Cout,
                                                   int Kdim, int Ndim) {
    __shared__ __align__(16) float As[16][128];
    __shared__ __align__(16) float Bs[16][64];

    const int tid = threadIdx.x;
    const int bm = blockIdx.y * 128;
    const int bn = blockIdx.x * 64;

    const float* Ap = (MODE == 2) ? g_Y : A;

    const int b_row = tid >> 4;         // 0..15
    const int b_n4  = (tid & 15) * 4;

    const int ty = tid >> 4;            // 0..15 -> rows ty*8..+7
    const int tx = tid & 15;            // 0..15 -> cols tx*4..+3

    float acc[8][4];
#pragma unroll
    for (int i = 0; i < 8; i++)
#pragma unroll
        for (int j = 0; j < 4; j++) acc[i][j] = 0.f;

    for (int k0 = 0; k0 < Kdim; k0 += 16) {
        // Load A tile (128x16), transposed into As[k][m]
#pragma unroll
        for (int it = 0; it < 2; it++) {
            int idx = tid + it * 256;
            int row = idx >> 2;
            int k4  = (idx & 3) * 4;
            float4 av = *(const float4*)(Ap + (size_t)(bm + row) * Kdim + k0 + k4);
            As[k4 + 0][row] = av.x;
            As[k4 + 1][row] = av.y;
            As[k4 + 2][row] = av.z;
            As[k4 + 3][row] = av.w;
        }
        // Load B tile (16x64)
        {
            float4 bv = *(const float4*)(Bm + (size_t)(k0 + b_row) * Ndim + bn + b_n4);
            *(float4*)&Bs[b_row][b_n4] = bv;
        }
        __syncthreads();

#pragma unroll
        for (int k = 0; k < 16; k++) {
            float a[8], b[4];
            float4 a0 = *(const float4*)&As[k][ty * 8];
            float4 a1 = *(const float4*)&As[k][ty * 8 + 4];
            a[0]=a0.x; a[1]=a0.y; a[2]=a0.z; a[3]=a0.w;
            a[4]=a1.x; a[5]=a1.y; a[6]=a1.z; a[7]=a1.w;
            float4 b0 = *(const float4*)&Bs[k][tx * 4];
            b[0]=b0.x; b[1]=b0.y; b[2]=b0.z; b[3]=b0.w;
#pragma unroll
            for (int i = 0; i < 8; i++)
#pragma unroll
                for (int j = 0; j < 4; j++) acc[i][j] += a[i] * b[j];
        }
        __syncthreads();
    }

    if (MODE == 2) {
#pragma unroll
        for (int i = 0; i < 8; i++) {
            int m = bm + ty * 8 + i;
            float4 v = make_float4(acc[i][0], acc[i][1], acc[i][2], acc[i][3]);
            *(float4*)(Cout + (size_t)m * Ndim + bn + tx * 4) = v;
        }
    } else {
        // QKV scatter. Within one 64-wide N tile: matrix + head are constant.
        int which = bn >> 10;             // 0=Q 1=K 2=V
        int h     = (bn & 1023) >> 6;
        float* dst = (which == 0) ? g_Q : (which == 1) ? g_K : g_V;
#pragma unroll
        for (int i = 0; i < 8; i++) {
            int m = bm + ty * 8 + i;
            int b = m >> 11;              // / T
            int t = m & 2047;
            float4 v = make_float4(acc[i][0], acc[i][1], acc[i][2], acc[i][3]);
            *(float4*)(dst + (((size_t)(b * HH + h) * TT + t) * DD) + tx * 4) = v;
        }
    }
}

// ---------------------------------------------------------------------------
// Flash attention, fp32. 1 thread == 1 query row. BQ=128 rows/CTA, BK=64.
// Dynamic smem: Ks[64][64] + Vs[64][64] + Ss[128][65] = 66048 bytes.
// ---------------------------------------------------------------------------
__global__ __launch_bounds__(128) void attn_kernel() {
    extern __shared__ float sm[];
    float (*Ks)[64] = (float(*)[64])sm;             // 4096 floats
    float (*Vs)[64] = (float(*)[64])(sm + 4096);    // 4096 floats
    float (*Ss)[65] = (float(*)[65])(sm + 8192);    // 8320 floats

    const int r  = threadIdx.x;
    const int qt = (gridDim.x - 1) - blockIdx.x;    // longest work first
    const int bh = blockIdx.y;                       // b*H + h
    const int tq = qt * 128 + r;

    const float* qp = g_Q + ((size_t)bh * TT + tq) * DD;
    float q[64];
#pragma unroll
    for (int i = 0; i < 16; i++) {
        float4 v = *(const float4*)(qp + 4 * i);
        q[4*i+0] = v.x * 0.125f;   // 1/sqrt(64)
        q[4*i+1] = v.y * 0.125f;
        q[4*i+2] = v.z * 0.125f;
        q[4*i+3] = v.w * 0.125f;
    }

    float acc[64];
#pragma unroll
    for (int d = 0; d < 64; d++) acc[d] = 0.f;
    float m = -1e30f, l = 0.f;

    const float* kb = g_K + (size_t)bh * TT * DD;
    const float* vb = g_V + (size_t)bh * TT * DD;

    const int nkt = 2 * qt + 2;   // number of 64-key tiles (covers rows up to qt*128+127)
    for (int kt = 0; kt < nkt; kt++) {
        // Cooperative load of K,V tiles (64x64 each)
#pragma unroll
        for (int t = 0; t < 8; t++) {
            int f = r + t * 128;
            int row = f >> 4;
            int c   = (f & 15) * 4;
            *(float4*)&Ks[row][c] = *(const float4*)(kb + (size_t)(kt * 64 + row) * 64 + c);
            *(float4*)&Vs[row][c] = *(const float4*)(vb + (size_t)(kt * 64 + row) * 64 + c);
        }
        __syncthreads();

        const int kbase = kt * 64;
        if (kbase <= tq) {
            const int jmax = min(64, tq - kbase + 1);
            // Pass 1: scores + tile max
            float tmax = -1e30f;
            for (int j = 0; j < jmax; j++) {
                const float4* krow = (const float4*)Ks[j];
                float s0 = 0.f, s1 = 0.f, s2 = 0.f, s3 = 0.f;
#pragma unroll
                for (int i = 0; i < 16; i++) {
                    float4 kv = krow[i];
                    s0 += q[4*i+0] * kv.x;
                    s1 += q[4*i+1] * kv.y;
                    s2 += q[4*i+2] * kv.z;
                    s3 += q[4*i+3] * kv.w;
                }
                float s = (s0 + s1) + (s2 + s3);
                tmax = fmaxf(tmax, s);
                Ss[r][j] = s;
            }
            float mnew  = fmaxf(m, tmax);
            float alpha = __expf(m - mnew);
            l *= alpha;
#pragma unroll
            for (int d = 0; d < 64; d++) acc[d] *= alpha;

            // Pass 2: exp + PV accumulate
            float lsum = 0.f;
            for (int j = 0; j < jmax; j++) {
                float p = __expf(Ss[r][j] - mnew);
                lsum += p;
                const float4* vrow = (const float4*)Vs[j];
#pragma unroll
                for (int i = 0; i < 16; i++) {
                    float4 vv = vrow[i];
                    acc[4*i+0] += p * vv.x;
                    acc[4*i+1] += p * vv.y;
                    acc[4*i+2] += p * vv.z;
                    acc[4*i+3] += p * vv.w;
                }
            }
            l += lsum;
            m = mnew;
        }
        __syncthreads();
    }

    const float inv = 1.0f / l;
    const int b = bh >> 4;
    const int h = bh & 15;
    float* yp = g_Y + ((size_t)(b * TT + tq)) * CC + h * DD;
#pragma unroll
    for (int i = 0; i < 16; i++) {
        float4 v = make_float4(acc[4*i+0]*inv, acc[4*i+1]*inv, acc[4*i+2]*inv, acc[4*i+3]*inv);
        *(float4*)(yp + 4 * i) = v;
    }
}

// ---------------------------------------------------------------------------
// Launch
// ---------------------------------------------------------------------------
extern "C" void kernel_launch(void* const* d_in, const int* in_sizes, int n_in,
                              void* d_out, int out_size) {
    const float* X     = (const float*)d_in[0];   // (B,T,C)
    const float* Wqkv  = (const float*)d_in[1];   // (C,3C)
    const float* Wproj = (const float*)d_in[2];   // (C,C)
    float* out = (float*)d_out;                   // (B,T,C)

    // Attention needs 66048B dynamic smem (> 48KB default). Idempotent, capture-safe.
    cudaFuncSetAttribute(attn_kernel, cudaFuncAttributeMaxDynamicSharedMemorySize, 66048);

    // 1) QKV = X @ W_qkv, scattered into [B,H,T,64] Q/K/V
    gemm_kernel<1><<<dim3(NQKV / 64, MM / 128), 256>>>(X, Wqkv, nullptr, CC, NQKV);

    // 2) Causal flash attention -> g_Y ([B,T,C])
    attn_kernel<<<dim3(TT / 128, BB * HH), 128, 66048>>>();

    // 3) out = g_Y @ W_proj
    gemm_kernel<2><<<dim3(CC / 64, MM / 128), 256>>>(nullptr, Wproj, out, CC, CC);
}

// round 2
// speedup vs baseline: 1.0821x; 1.0821x over previous
#include <cuda_runtime.h>
#include <cuda_bf16.h>
#include <cstdint>

// Problem constants
#define BB   2
#define TT   2048
#define CC   1024
#define HH   16
#define DD   64
#define MM   (BB*TT)        // 4096
#define NQKV (3*CC)         // 3072

// Scratch (device globals: allocation-free rule)
__device__ float g_Q[(size_t)BB*HH*TT*DD];   // [B,H,T,64]
__device__ float g_K[(size_t)BB*HH*TT*DD];
__device__ float g_V[(size_t)BB*HH*TT*DD];
__device__ float g_Y[(size_t)MM*CC];         // [B,T,C] attention output

// ---------------------------------------------------------------------------
// PTX helpers
// ---------------------------------------------------------------------------
__device__ __forceinline__ void cpa16(uint32_t saddr, const void* gptr) {
    asm volatile("cp.async.cg.shared.global [%0], [%1], 16;\n" :: "r"(saddr), "l"(gptr));
}
__device__ __forceinline__ void cpa_commit() { asm volatile("cp.async.commit_group;\n"); }

__device__ __forceinline__ uint32_t f2tf32(uint32_t bits) {
    uint32_t r; float f = __uint_as_float(bits);
    asm("cvt.rna.tf32.f32 %0, %1;\n" : "=r"(r) : "f"(f));
    return r;
}
__device__ __forceinline__ uint32_t f2tf32f(float f) {
    uint32_t r;
    asm("cvt.rna.tf32.f32 %0, %1;\n" : "=r"(r) : "f"(f));
    return r;
}
__device__ __forceinline__ void ldsm_x4(uint32_t addr, uint32_t& x0, uint32_t& x1,
                                        uint32_t& x2, uint32_t& x3) {
    asm volatile("ldmatrix.sync.aligned.m8n8.x4.shared.b16 {%0,%1,%2,%3}, [%4];\n"
                 : "=r"(x0), "=r"(x1), "=r"(x2), "=r"(x3) : "r"(addr));
}
__device__ __forceinline__ void mma_tf32(float* c, const uint32_t* a, const uint32_t* b) {
    asm volatile(
        "mma.sync.aligned.m16n8k8.row.col.f32.tf32.tf32.f32 "
        "{%0,%1,%2,%3}, {%4,%5,%6,%7}, {%8,%9}, {%0,%1,%2,%3};\n"
        : "+f"(c[0]), "+f"(c[1]), "+f"(c[2]), "+f"(c[3])
        : "r"(a[0]), "r"(a[1]), "r"(a[2]), "r"(a[3]), "r"(b[0]), "r"(b[1]));
}

// ---------------------------------------------------------------------------
// tf32 tensor-core GEMM: C[M,N] = A[M,K] @ B[K,N]
// BM=128, BN=128, BK=32, 256 threads (8 warps, 2x4 warp grid, 64x32 warp tile)
// MODE 1: QKV gemm -> scatter into g_Q/g_K/g_V ([B,H,T,64])
// MODE 2: proj gemm (A = g_Y) -> store to Cout
// Dynamic smem: A 2x128x36 + B 2x32x136 floats = 71680 bytes (double buffered)
// ---------------------------------------------------------------------------
#define AS_STRIDE 36
#define BS_STRIDE 136
#define AS_SZ     (128*AS_STRIDE)   // floats per buffer
#define BS_SZ     (32*BS_STRIDE)
#define GEMM_SMEM ((2*AS_SZ + 2*BS_SZ)*4)

template <int MODE>
__global__ __launch_bounds__(256, 2) void gemm_tf32(const float* __restrict__ A,
                                                    const float* __restrict__ Bm,
                                                    float* __restrict__ Cout,
                                                    int Kdim, int Ndim) {
    extern __shared__ float sm[];
    float* As = sm;                 // [2][128][36]
    float* Bs = sm + 2*AS_SZ;       // [2][32][136]

    const int tid  = threadIdx.x;
    const int lane = tid & 31;
    const int warp = tid >> 5;
    const int wm = (warp >> 2) * 64;   // 0,64
    const int wn = (warp & 3) * 32;    // 0,32,64,96
    const int bm = blockIdx.y * 128;
    const int bn = blockIdx.x * 128;

    const float* Ap = (MODE == 2) ? g_Y : A;

    const uint32_t as_u = (uint32_t)__cvta_generic_to_shared(As);

    float acc[4][4][4];
#pragma unroll
    for (int mi = 0; mi < 4; mi++)
#pragma unroll
        for (int ni = 0; ni < 4; ni++)
#pragma unroll
            for (int r = 0; r < 4; r++) acc[mi][ni][r] = 0.f;

    const int KT = Kdim / 32;

    // ---- loader lambda (cp.async 16B) ----
    auto load_tiles = [&](int buf, int k0) {
        const uint32_t a_base = as_u + (uint32_t)(buf * AS_SZ * 4);
        const uint32_t b_base = as_u + (uint32_t)((2*AS_SZ + buf * BS_SZ) * 4);
#pragma unroll
        for (int i = 0; i < 4; i++) {
            int idx = tid + i * 256;             // 0..1023
            int row = idx >> 3;                  // 0..127
            int c4  = idx & 7;                   // 0..7
            cpa16(a_base + (uint32_t)((row * AS_STRIDE + c4 * 4) * 4),
                  Ap + (size_t)(bm + row) * Kdim + k0 + c4 * 4);
        }
#pragma unroll
        for (int i = 0; i < 4; i++) {
            int idx = tid + i * 256;
            int row = idx >> 5;                  // 0..31
            int c4  = idx & 31;                  // 0..31
            cpa16(b_base + (uint32_t)((row * BS_STRIDE + c4 * 4) * 4),
                  Bm + (size_t)(k0 + row) * Ndim + bn + c4 * 4);
        }
        cpa_commit();
    };

    load_tiles(0, 0);

    for (int kt = 0; kt < KT; kt++) {
        const int buf = kt & 1;
        if (kt + 1 < KT) {
            load_tiles(buf ^ 1, (kt + 1) * 32);
            asm volatile("cp.async.wait_group 1;\n");
        } else {
            asm volatile("cp.async.wait_group 0;\n");
        }
        __syncthreads();

        const uint32_t a_base = as_u + (uint32_t)(buf * AS_SZ * 4);
        const float* Bsb = Bs + buf * BS_SZ;

#pragma unroll
        for (int s = 0; s < 4; s++) {
            uint32_t afr[4][4];
#pragma unroll
            for (int mi = 0; mi < 4; mi++) {
                uint32_t addr = a_base +
                    (uint32_t)(((wm + mi * 16 + (lane & 15)) * AS_STRIDE +
                                s * 8 + (lane >> 4) * 4) * 4);
                ldsm_x4(addr, afr[mi][0], afr[mi][1], afr[mi][2], afr[mi][3]);
            }
#pragma unroll
            for (int mi = 0; mi < 4; mi++)
#pragma unroll
                for (int r = 0; r < 4; r++) afr[mi][r] = f2tf32(afr[mi][r]);

            uint32_t bfr[4][2];
#pragma unroll
            for (int ni = 0; ni < 4; ni++) {
                int col = wn + ni * 8 + (lane >> 2);
                float b0 = Bsb[(s * 8 + (lane & 3)) * BS_STRIDE + col];
                float b1 = Bsb[(s * 8 + 4 + (lane & 3)) * BS_STRIDE + col];
                bfr[ni][0] = f2tf32f(b0);
                bfr[ni][1] = f2tf32f(b1);
            }
#pragma unroll
            for (int mi = 0; mi < 4; mi++)
#pragma unroll
                for (int ni = 0; ni < 4; ni++)
                    mma_tf32(acc[mi][ni], afr[mi], bfr[ni]);
        }
        __syncthreads();
    }

    // ---- epilogue ----
    const int g  = lane >> 2;
    const int tc = lane & 3;
#pragma unroll
    for (int mi = 0; mi < 4; mi++) {
#pragma unroll
        for (int ni = 0; ni < 4; ni++) {
            int ncol = bn + wn + ni * 8 + 2 * tc;
#pragma unroll
            for (int half = 0; half < 2; half++) {
                int mrow = bm + wm + mi * 16 + g + half * 8;
                float2 v = make_float2(acc[mi][ni][half * 2], acc[mi][ni][half * 2 + 1]);
                if (MODE == 2) {
                    *(float2*)(Cout + (size_t)mrow * Ndim + ncol) = v;
                } else {
                    int which = ncol >> 10;
                    int h     = (ncol & 1023) >> 6;
                    int d     = ncol & 63;
                    int b     = mrow >> 11;
                    int t     = mrow & 2047;
                    float* dst = (which == 0) ? g_Q : (which == 1) ? g_K : g_V;
                    *(float2*)(dst + (((size_t)(b * HH + h) * TT + t) * DD) + d) = v;
                }
            }
        }
    }
}

// ---------------------------------------------------------------------------
// Flash attention, fp32. 2 threads per query row (each owns 32 of 64 dims).
// 256 threads = 128 rows/CTA. BK=64 keys/tile, register-chunked online softmax.
// Static smem: Ks[64][64] + Vs[64][64] = 32 KB.
// ---------------------------------------------------------------------------
__global__ __launch_bounds__(256, 2) void attn_kernel() {
    __shared__ float Ks[64][64];
    __shared__ float Vs[64][64];

    const int tid  = threadIdx.x;
    const int row  = tid >> 1;
    const int half = tid & 1;
    const int qt = (gridDim.x - 1) - blockIdx.x;    // longest work first
    const int bh = blockIdx.y;                       // b*H + h
    const int tq = qt * 128 + row;

    // top row handled by this warp (rows are 16 consecutive per warp)
    const int warp_top_row = ((tid >> 5) << 4) + 15;
    const int tq_hi = qt * 128 + warp_top_row;

    const float* qp = g_Q + ((size_t)bh * TT + tq) * DD + half * 32;
    float q[32];
#pragma unroll
    for (int i = 0; i < 8; i++) {
        float4 v = *(const float4*)(qp + 4 * i);
        q[4*i+0] = v.x * 0.125f;   // 1/sqrt(64)
        q[4*i+1] = v.y * 0.125f;
        q[4*i+2] = v.z * 0.125f;
        q[4*i+3] = v.w * 0.125f;
    }

    float acc[32];
#pragma unroll
    for (int d = 0; d < 32; d++) acc[d] = 0.f;
    float m = -1e30f, l = 0.f;

    const float* kb = g_K + (size_t)bh * TT * DD;
    const float* vb = g_V + (size_t)bh * TT * DD;

    const int nkt = 2 * qt + 2;
    for (int kt = 0; kt < nkt; kt++) {
        // Cooperative load of K,V tiles (64x64 each), 256 threads x 4 float4 each
#pragma unroll
        for (int t = 0; t < 4; t++) {
            int f = tid + t * 256;
            int r = f >> 4;
            int c = (f & 15) * 4;
            *(float4*)&Ks[r][c] = *(const float4*)(kb + (size_t)(kt * 64 + r) * 64 + c);
            *(float4*)&Vs[r][c] = *(const float4*)(vb + (size_t)(kt * 64 + r) * 64 + c);
        }
        __syncthreads();

        const int kbase = kt * 64;
        const int jmaxw = min(64, tq_hi - kbase + 1);  // warp-uniform
        const int jmax_l = tq - kbase + 1;             // per-lane valid count

        if (jmaxw > 0) {
            for (int j0 = 0; j0 < jmaxw; j0 += 8) {
                const int jnw = min(8, jmaxw - j0);     // warp-uniform
                float s[8];
                float cmax = -1e30f;
#pragma unroll
                for (int jj = 0; jj < 8; jj++) {
                    if (jj < jnw) {
                        const float4* kr = (const float4*)&Ks[j0 + jj][half * 32];
                        float s0 = 0.f, s1 = 0.f, s2 = 0.f, s3 = 0.f;
#pragma unroll
                        for (int i = 0; i < 8; i++) {
                            float4 kv = kr[i];
                            s0 += q[4*i+0] * kv.x;
                            s1 += q[4*i+1] * kv.y;
                            s2 += q[4*i+2] * kv.z;
                            s3 += q[4*i+3] * kv.w;
                        }
                        float ps = (s0 + s1) + (s2 + s3);
                        float sv = ps + __shfl_xor_sync(0xffffffffu, ps, 1);
                        bool ok = (j0 + jj) < jmax_l;
                        s[jj] = ok ? sv : -1e30f;
                        cmax = fmaxf(cmax, s[jj]);
                    }
                }
                // per-lane state update (no shfl below -> divergence safe)
                if (j0 < jmax_l) {
                    float mnew  = fmaxf(m, cmax);
                    float alpha = __expf(m - mnew);
                    l *= alpha;
#pragma unroll
                    for (int d = 0; d < 32; d++) acc[d] *= alpha;
#pragma unroll
                    for (int jj = 0; jj < 8; jj++) {
                        if (jj < jnw) {
                            float p = __expf(s[jj] - mnew);  // masked -> 0
                            l += p;
                            const float4* vr = (const float4*)&Vs[j0 + jj][half * 32];
#pragma unroll
                            for (int i = 0; i < 8; i++) {
                                float4 vv = vr[i];
                                acc[4*i+0] += p * vv.x;
                                acc[4*i+1] += p * vv.y;
                                acc[4*i+2] += p * vv.z;
                                acc[4*i+3] += p * vv.w;
                            }
                        }
                    }
                    m = mnew;
                }
            }
        }
        __syncthreads();
    }

    const float inv = 1.0f / l;
    const int b = bh >> 4;
    const int h = bh & 15;
    float* yp = g_Y + ((size_t)(b * TT + tq)) * CC + h * DD + half * 32;
#pragma unroll
    for (int i = 0; i < 8; i++) {
        float4 v = make_float4(acc[4*i+0]*inv, acc[4*i+1]*inv, acc[4*i+2]*inv, acc[4*i+3]*inv);
        *(float4*)(yp + 4 * i) = v;
    }
}

// ---------------------------------------------------------------------------
// Launch
// ---------------------------------------------------------------------------
extern "C" void kernel_launch(void* const* d_in, const int* in_sizes, int n_in,
                              void* d_out, int out_size) {
    const float* X     = (const float*)d_in[0];   // (B,T,C)
    const float* Wqkv  = (const float*)d_in[1];   // (C,3C)
    const float* Wproj = (const float*)d_in[2];   // (C,C)
    float* out = (float*)d_out;                   // (B,T,C)

    cudaFuncSetAttribute(gemm_tf32<1>, cudaFuncAttributeMaxDynamicSharedMemorySize, GEMM_SMEM);
    cudaFuncSetAttribute(gemm_tf32<2>, cudaFuncAttributeMaxDynamicSharedMemorySize, GEMM_SMEM);

    // 1) QKV = X @ W_qkv, scattered into [B,H,T,64] Q/K/V
    gemm_tf32<1><<<dim3(NQKV / 128, MM / 128), 256, GEMM_SMEM>>>(X, Wqkv, nullptr, CC, NQKV);

    // 2) Causal flash attention -> g_Y ([B,T,C])
    attn_kernel<<<dim3(TT / 128, BB * HH), 256>>>();

    // 3) out = g_Y @ W_proj
    gemm_tf32<2><<<dim3(CC / 128, MM / 128), 256, GEMM_SMEM>>>(nullptr, Wproj, out, CC, CC);
}

// round 4
// speedup vs baseline: 3.4070x; 3.1484x over previous
#include <cuda_runtime.h>
#include <cuda_bf16.h>
#include <cstdint>

// Problem constants
#define BB   2
#define TT   2048
#define CC   1024
#define HH   16
#define DD   64
#define MM   (BB*TT)        // 4096
#define NQKV (3*CC)         // 3072

// Scratch (device globals: allocation-free rule)
__device__ float g_Q[(size_t)BB*HH*TT*DD];   // [B,H,T,64]
__device__ float g_K[(size_t)BB*HH*TT*DD];
__device__ float g_V[(size_t)BB*HH*TT*DD];
__device__ float g_Y[(size_t)MM*CC];         // [B,T,C] attention output

// ---------------------------------------------------------------------------
// PTX helpers
// ---------------------------------------------------------------------------
__device__ __forceinline__ void cpa16(uint32_t saddr, const void* gptr) {
    asm volatile("cp.async.cg.shared.global [%0], [%1], 16;\n" :: "r"(saddr), "l"(gptr));
}
__device__ __forceinline__ void cpa_commit() { asm volatile("cp.async.commit_group;\n"); }

__device__ __forceinline__ uint32_t f2tf32(uint32_t bits) {
    uint32_t r; float f = __uint_as_float(bits);
    asm("cvt.rna.tf32.f32 %0, %1;\n" : "=r"(r) : "f"(f));
    return r;
}
__device__ __forceinline__ uint32_t f2tf32f(float f) {
    uint32_t r;
    asm("cvt.rna.tf32.f32 %0, %1;\n" : "=r"(r) : "f"(f));
    return r;
}
__device__ __forceinline__ void ldsm_x4(uint32_t addr, uint32_t& x0, uint32_t& x1,
                                        uint32_t& x2, uint32_t& x3) {
    asm volatile("ldmatrix.sync.aligned.m8n8.x4.shared.b16 {%0,%1,%2,%3}, [%4];\n"
                 : "=r"(x0), "=r"(x1), "=r"(x2), "=r"(x3) : "r"(addr));
}
__device__ __forceinline__ void mma_tf32(float* c, const uint32_t* a, const uint32_t* b) {
    asm volatile(
        "mma.sync.aligned.m16n8k8.row.col.f32.tf32.tf32.f32 "
        "{%0,%1,%2,%3}, {%4,%5,%6,%7}, {%8,%9}, {%0,%1,%2,%3};\n"
        : "+f"(c[0]), "+f"(c[1]), "+f"(c[2]), "+f"(c[3])
        : "r"(a[0]), "r"(a[1]), "r"(a[2]), "r"(a[3]), "r"(b[0]), "r"(b[1]));
}

// ---------------------------------------------------------------------------
// tf32 tensor-core GEMM: C[M,N] = A[M,K] @ B[K,N]
// BM=128, BN=128, BK=32, 256 threads (8 warps, 2x4 warp grid, 64x32 warp tile)
// ---------------------------------------------------------------------------
#define AS_STRIDE 36
#define BS_STRIDE 136
#define AS_SZ     (128*AS_STRIDE)
#define BS_SZ     (32*BS_STRIDE)
#define GEMM_SMEM ((2*AS_SZ + 2*BS_SZ)*4)

template <int MODE>
__global__ __launch_bounds__(256, 2) void gemm_tf32(const float* __restrict__ A,
                                                    const float* __restrict__ Bm,
                                                    float* __restrict__ Cout,
                                                    int Kdim, int Ndim) {
    extern __shared__ float sm[];
    float* Bs = sm + 2*AS_SZ;

    const int tid  = threadIdx.x;
    const int lane = tid & 31;
    const int warp = tid >> 5;
    const int wm = (warp >> 2) * 64;
    const int wn = (warp & 3) * 32;
    const int bm = blockIdx.y * 128;
    const int bn = blockIdx.x * 128;

    const float* Ap = (MODE == 2) ? g_Y : A;
    const uint32_t as_u = (uint32_t)__cvta_generic_to_shared(sm);

    float acc[4][4][4];
#pragma unroll
    for (int mi = 0; mi < 4; mi++)
#pragma unroll
        for (int ni = 0; ni < 4; ni++)
#pragma unroll
            for (int r = 0; r < 4; r++) acc[mi][ni][r] = 0.f;

    const int KT = Kdim / 32;

    auto load_tiles = [&](int buf, int k0) {
        const uint32_t a_base = as_u + (uint32_t)(buf * AS_SZ * 4);
        const uint32_t b_base = as_u + (uint32_t)((2*AS_SZ + buf * BS_SZ) * 4);
#pragma unroll
        for (int i = 0; i < 4; i++) {
            int idx = tid + i * 256;
            int row = idx >> 3;
            int c4  = idx & 7;
            cpa16(a_base + (uint32_t)((row * AS_STRIDE + c4 * 4) * 4),
                  Ap + (size_t)(bm + row) * Kdim + k0 + c4 * 4);
        }
#pragma unroll
        for (int i = 0; i < 4; i++) {
            int idx = tid + i * 256;
            int row = idx >> 5;
            int c4  = idx & 31;
            cpa16(b_base + (uint32_t)((row * BS_STRIDE + c4 * 4) * 4),
                  Bm + (size_t)(k0 + row) * Ndim + bn + c4 * 4);
        }
        cpa_commit();
    };

    load_tiles(0, 0);

    for (int kt = 0; kt < KT; kt++) {
        const int buf = kt & 1;
        if (kt + 1 < KT) {
            load_tiles(buf ^ 1, (kt + 1) * 32);
            asm volatile("cp.async.wait_group 1;\n");
        } else {
            asm volatile("cp.async.wait_group 0;\n");
        }
        __syncthreads();

        const uint32_t a_base = as_u + (uint32_t)(buf * AS_SZ * 4);
        const float* Bsb = Bs + buf * BS_SZ;

#pragma unroll
        for (int s = 0; s < 4; s++) {
            uint32_t afr[4][4];
#pragma unroll
            for (int mi = 0; mi < 4; mi++) {
                uint32_t addr = a_base +
                    (uint32_t)(((wm + mi * 16 + (lane & 15)) * AS_STRIDE +
                                s * 8 + (lane >> 4) * 4) * 4);
                ldsm_x4(addr, afr[mi][0], afr[mi][1], afr[mi][2], afr[mi][3]);
            }
#pragma unroll
            for (int mi = 0; mi < 4; mi++)
#pragma unroll
                for (int r = 0; r < 4; r++) afr[mi][r] = f2tf32(afr[mi][r]);

            uint32_t bfr[4][2];
#pragma unroll
            for (int ni = 0; ni < 4; ni++) {
                int col = wn + ni * 8 + (lane >> 2);
                float b0 = Bsb[(s * 8 + (lane & 3)) * BS_STRIDE + col];
                float b1 = Bsb[(s * 8 + 4 + (lane & 3)) * BS_STRIDE + col];
                bfr[ni][0] = f2tf32f(b0);
                bfr[ni][1] = f2tf32f(b1);
            }
#pragma unroll
            for (int mi = 0; mi < 4; mi++)
#pragma unroll
                for (int ni = 0; ni < 4; ni++)
                    mma_tf32(acc[mi][ni], afr[mi], bfr[ni]);
        }
        __syncthreads();
    }

    const int g  = lane >> 2;
    const int tc = lane & 3;
#pragma unroll
    for (int mi = 0; mi < 4; mi++) {
#pragma unroll
        for (int ni = 0; ni < 4; ni++) {
            int ncol = bn + wn + ni * 8 + 2 * tc;
#pragma unroll
            for (int half = 0; half < 2; half++) {
                int mrow = bm + wm + mi * 16 + g + half * 8;
                float2 v = make_float2(acc[mi][ni][half * 2], acc[mi][ni][half * 2 + 1]);
                if (MODE == 2) {
                    *(float2*)(Cout + (size_t)mrow * Ndim + ncol) = v;
                } else {
                    int which = ncol >> 10;
                    int h     = (ncol & 1023) >> 6;
                    int d     = ncol & 63;
                    int b     = mrow >> 11;
                    int t     = mrow & 2047;
                    float* dst = (which == 0) ? g_Q : (which == 1) ? g_K : g_V;
                    *(float2*)(dst + (((size_t)(b * HH + h) * TT + t) * DD) + d) = v;
                }
            }
        }
    }
}

// ---------------------------------------------------------------------------
// Tensor-core flash attention (tf32 mma), BQ=64, BK=64, 4 warps (m16 each).
// K/V staged in smem pre-rounded to tf32, pad 68 -> conflict-free B-frag LDS.
// ---------------------------------------------------------------------------
__global__ __launch_bounds__(128, 3) void attn_mma() {
    __shared__ float Ks[64][68];
    __shared__ float Vs[64][68];

    const int tid  = threadIdx.x;
    const int lane = tid & 31;
    const int warp = tid >> 5;                    // 0..3 -> rows warp*16..+15
    const int qt   = (int)(gridDim.x - 1 - blockIdx.x);  // longest first
    const int bh   = blockIdx.y;
    const int g    = lane >> 2;                   // 0..7
    const int tc   = lane & 3;                    // 0..3
    const unsigned FULL = 0xffffffffu;

    const int tq0 = qt * 64 + warp * 16 + g;      // row for c0/c1
    const int tq1 = tq0 + 8;                      // row for c2/c3

    // Q A-fragments, pre-scaled by 1/8, pre-rounded to tf32 (held all kernel)
    const float* qb = g_Q + (size_t)bh * TT * DD;
    uint32_t qa[8][4];
#pragma unroll
    for (int s = 0; s < 8; s++) {
        qa[s][0] = f2tf32f(qb[(size_t)tq0 * DD + 8*s + tc]     * 0.125f);
        qa[s][1] = f2tf32f(qb[(size_t)tq1 * DD + 8*s + tc]     * 0.125f);
        qa[s][2] = f2tf32f(qb[(size_t)tq0 * DD + 8*s + tc + 4] * 0.125f);
        qa[s][3] = f2tf32f(qb[(size_t)tq1 * DD + 8*s + tc + 4] * 0.125f);
    }

    float o[8][4];
#pragma unroll
    for (int od = 0; od < 8; od++)
#pragma unroll
        for (int r = 0; r < 4; r++) o[od][r] = 0.f;
    float m0 = -1e30f, m1 = -1e30f, l0 = 0.f, l1 = 0.f;

    const float* kb = g_K + (size_t)bh * TT * DD;
    const float* vb = g_V + (size_t)bh * TT * DD;

    const int nkt = qt + 1;
    for (int kt = 0; kt < nkt; kt++) {
        // ---- cooperative K/V tile load, tf32-rounded into padded smem ----
#pragma unroll
        for (int t = 0; t < 8; t++) {
            int f = tid + t * 128;          // 0..1023
            int r = f >> 4;                 // 0..63
            int c = (f & 15) * 4;           // 0..60
            float4 k4 = *(const float4*)(kb + (size_t)(kt*64 + r) * DD + c);
            float4 v4 = *(const float4*)(vb + (size_t)(kt*64 + r) * DD + c);
            Ks[r][c+0] = __uint_as_float(f2tf32f(k4.x));
            Ks[r][c+1] = __uint_as_float(f2tf32f(k4.y));
            Ks[r][c+2] = __uint_as_float(f2tf32f(k4.z));
            Ks[r][c+3] = __uint_as_float(f2tf32f(k4.w));
            Vs[r][c+0] = __uint_as_float(f2tf32f(v4.x));
            Vs[r][c+1] = __uint_as_float(f2tf32f(v4.y));
            Vs[r][c+2] = __uint_as_float(f2tf32f(v4.z));
            Vs[r][c+3] = __uint_as_float(f2tf32f(v4.w));
        }
        __syncthreads();

        const bool masked = (kt == qt);              // only last tile is partial
        const int kbase = kt * 64;
        const int ntc = masked ? (warp * 2 + 2) : 8; // valid 8-key chunks for this warp

        // ---- S = Q K^T for this tile ----
        float sc[8][4];
        for (int nt = 0; nt < ntc; nt++) {
            float c4[4] = {0.f, 0.f, 0.f, 0.f};
            const float* krow = &Ks[8*nt + g][0];    // B-frag n-index = g
#pragma unroll
            for (int s = 0; s < 8; s++) {
                uint32_t b2[2];
                b2[0] = __float_as_uint(krow[8*s + tc]);
                b2[1] = __float_as_uint(krow[8*s + tc + 4]);
                mma_tf32(c4, qa[s], b2);
            }
            if (masked) {
                int k0 = kbase + 8*nt + 2*tc;
                if (k0     > tq0) c4[0] = -1e30f;
                if (k0 + 1 > tq0) c4[1] = -1e30f;
                if (k0     > tq1) c4[2] = -1e30f;
                if (k0 + 1 > tq1) c4[3] = -1e30f;
            }
            sc[nt][0] = c4[0]; sc[nt][1] = c4[1]; sc[nt][2] = c4[2]; sc[nt][3] = c4[3];
        }

        // ---- online softmax (per-row state, quad-replicated) ----
        float rm0 = -1e30f, rm1 = -1e30f;
        for (int nt = 0; nt < ntc; nt++) {
            rm0 = fmaxf(rm0, fmaxf(sc[nt][0], sc[nt][1]));
            rm1 = fmaxf(rm1, fmaxf(sc[nt][2], sc[nt][3]));
        }
        rm0 = fmaxf(rm0, __shfl_xor_sync(FULL, rm0, 1));
        rm0 = fmaxf(rm0, __shfl_xor_sync(FULL, rm0, 2));
        rm1 = fmaxf(rm1, __shfl_xor_sync(FULL, rm1, 1));
        rm1 = fmaxf(rm1, __shfl_xor_sync(FULL, rm1, 2));
        const float m0n = fmaxf(m0, rm0);
        const float m1n = fmaxf(m1, rm1);
        const float a0 = __expf(m0 - m0n);
        const float a1 = __expf(m1 - m1n);
        l0 *= a0; l1 *= a1;
#pragma unroll
        for (int od = 0; od < 8; od++) {
            o[od][0] *= a0; o[od][1] *= a0;
            o[od][2] *= a1; o[od][3] *= a1;
        }
        m0 = m0n; m1 = m1n;

        // ---- P = exp(S - m), rearrange C-layout -> A-layout, PV mma ----
        const int src_lo = (lane & ~3) | (tc >> 1);
        const int src_hi = src_lo | 2;
        const bool odd = tc & 1;
        for (int nt = 0; nt < ntc; nt++) {
            float p0 = __expf(sc[nt][0] - m0n);
            float p1 = __expf(sc[nt][1] - m0n);
            float p2 = __expf(sc[nt][2] - m1n);
            float p3 = __expf(sc[nt][3] - m1n);
            l0 += p0 + p1; l1 += p2 + p3;

            float x0 = __shfl_sync(FULL, p0, src_lo);
            float x1 = __shfl_sync(FULL, p1, src_lo);
            float y0 = __shfl_sync(FULL, p0, src_hi);
            float y1 = __shfl_sync(FULL, p1, src_hi);
            float z0 = __shfl_sync(FULL, p2, src_lo);
            float z1 = __shfl_sync(FULL, p3, src_lo);
            float w0 = __shfl_sync(FULL, p2, src_hi);
            float w1 = __shfl_sync(FULL, p3, src_hi);

            uint32_t pa[4];
            pa[0] = f2tf32f(odd ? x1 : x0);   // (row g,   key 8nt+tc)
            pa[1] = f2tf32f(odd ? z1 : z0);   // (row g+8, key 8nt+tc)
            pa[2] = f2tf32f(odd ? y1 : y0);   // (row g,   key 8nt+tc+4)
            pa[3] = f2tf32f(odd ? w1 : w0);   // (row g+8, key 8nt+tc+4)

            const float* v0 = &Vs[8*nt + tc][0];
            const float* v1 = &Vs[8*nt + tc + 4][0];
#pragma unroll
            for (int od = 0; od < 8; od++) {
                uint32_t b2[2];
                b2[0] = __float_as_uint(v0[8*od + g]);
                b2[1] = __float_as_uint(v1[8*od + g]);
                mma_tf32(o[od], pa, b2);
            }
        }
        __syncthreads();
    }

    // ---- finalize: row-sum l across quad, normalize, write [B,T,C] ----
    l0 += __shfl_xor_sync(FULL, l0, 1);
    l0 += __shfl_xor_sync(FULL, l0, 2);
    l1 += __shfl_xor_sync(FULL, l1, 1);
    l1 += __shfl_xor_sync(FULL, l1, 2);
    const float inv0 = 1.0f / l0;
    const float inv1 = 1.0f / l1;

    const int b = bh >> 4;
    const int h = bh & 15;
    float* y0p = g_Y + ((size_t)(b * TT + tq0)) * CC + h * DD;
    float* y1p = g_Y + ((size_t)(b * TT + tq1)) * CC + h * DD;
#pragma unroll
    for (int od = 0; od < 8; od++) {
        *(float2*)(y0p + 8*od + 2*tc) = make_float2(o[od][0]*inv0, o[od][1]*inv0);
        *(float2*)(y1p + 8*od + 2*tc) = make_float2(o[od][2]*inv1, o[od][3]*inv1);
    }
}

// ---------------------------------------------------------------------------
// Launch
// ---------------------------------------------------------------------------
extern "C" void kernel_launch(void* const* d_in, const int* in_sizes, int n_in,
                              void* d_out, int out_size) {
    const float* X     = (const float*)d_in[0];   // (B,T,C)
    const float* Wqkv  = (const float*)d_in[1];   // (C,3C)
    const float* Wproj = (const float*)d_in[2];   // (C,C)
    float* out = (float*)d_out;                   // (B,T,C)

    cudaFuncSetAttribute(gemm_tf32<1>, cudaFuncAttributeMaxDynamicSharedMemorySize, GEMM_SMEM);
    cudaFuncSetAttribute(gemm_tf32<2>, cudaFuncAttributeMaxDynamicSharedMemorySize, GEMM_SMEM);

    // 1) QKV = X @ W_qkv, scattered into [B,H,T,64] Q/K/V
    gemm_tf32<1><<<dim3(NQKV / 128, MM / 128), 256, GEMM_SMEM>>>(X, Wqkv, nullptr, CC, NQKV);

    // 2) Causal flash attention (tensor cores) -> g_Y ([B,T,C])
    attn_mma<<<dim3(TT / 64, BB * HH), 128>>>();

    // 3) out = g_Y @ W_proj
    gemm_tf32<2><<<dim3(CC / 128, MM / 128), 256, GEMM_SMEM>>>(nullptr, Wproj, out, CC, CC);
}

// round 6
// speedup vs baseline: 3.4186x; 1.0034x over previous
#include <cuda_runtime.h>
#include <cuda_bf16.h>
#include <cstdint>

// Problem constants
#define BB   2
#define TT   2048
#define CC   1024
#define HH   16
#define DD   64
#define MM   (BB*TT)        // 4096
#define NQKV (3*CC)         // 3072

// Scratch (device globals, 64 MB total — same footprint as the passing R4)
__device__ float g_Q[(size_t)BB*HH*TT*DD];   // [B,H,T,64]  (tf32-rounded)
__device__ float g_K[(size_t)BB*HH*TT*DD];
__device__ float g_V[(size_t)BB*HH*TT*DD];
__device__ float g_Y[(size_t)MM*CC];         // phase 0-1: tf32-rounded X
                                             // phase 2-3: attn out (rounded)

// ---------------------------------------------------------------------------
// PTX helpers
// ---------------------------------------------------------------------------
__device__ __forceinline__ void cpa16(uint32_t saddr, const void* gptr) {
    asm volatile("cp.async.cg.shared.global [%0], [%1], 16;\n" :: "r"(saddr), "l"(gptr));
}
__device__ __forceinline__ void cpa_commit() { asm volatile("cp.async.commit_group;\n"); }

__device__ __forceinline__ uint32_t f2tf32f(float f) {
    uint32_t r;
    asm("cvt.rna.tf32.f32 %0, %1;\n" : "=r"(r) : "f"(f));
    return r;
}
__device__ __forceinline__ float roundtf(float f) {
    return __uint_as_float(f2tf32f(f));
}
__device__ __forceinline__ void ldsm_x4(uint32_t addr, uint32_t& x0, uint32_t& x1,
                                        uint32_t& x2, uint32_t& x3) {
    asm volatile("ldmatrix.sync.aligned.m8n8.x4.shared.b16 {%0,%1,%2,%3}, [%4];\n"
                 : "=r"(x0), "=r"(x1), "=r"(x2), "=r"(x3) : "r"(addr));
}
__device__ __forceinline__ void mma_tf32(float* c, const uint32_t* a, const uint32_t* b) {
    asm volatile(
        "mma.sync.aligned.m16n8k8.row.col.f32.tf32.tf32.f32 "
        "{%0,%1,%2,%3}, {%4,%5,%6,%7}, {%8,%9}, {%0,%1,%2,%3};\n"
        : "+f"(c[0]), "+f"(c[1]), "+f"(c[2]), "+f"(c[3])
        : "r"(a[0]), "r"(a[1]), "r"(a[2]), "r"(a[3]), "r"(b[0]), "r"(b[1]));
}

// ---------------------------------------------------------------------------
// Pre-round X to tf32 into g_Y (GEMM-1 reads it; attention later overwrites).
// 4096 blocks x 256 threads, 1 float4 each.
// ---------------------------------------------------------------------------
__global__ __launch_bounds__(256) void round_inputs(const float* __restrict__ X) {
    size_t idx = (size_t)blockIdx.x * 256 + threadIdx.x;
    float4 v = ((const float4*)X)[idx];
    v.x = roundtf(v.x); v.y = roundtf(v.y); v.z = roundtf(v.z); v.w = roundtf(v.w);
    ((float4*)g_Y)[idx] = v;
}

// ---------------------------------------------------------------------------
// tf32 tensor-core GEMM: C[M,N] = g_Y[M,K] @ B[K,N]
// A (g_Y) is pre-rounded -> no A-side cvt. B fragments cvt'd at load (32/ktile).
// BM=128, BN=128, BK=32, 256 thr, 8 warps.
// MODE 1: B=W_qkv -> rounded scatter into g_Q/g_K/g_V
// MODE 2: B=W_proj -> raw fp32 store to Cout
// ---------------------------------------------------------------------------
#define AS_STRIDE 36
#define BS_STRIDE 136
#define AS_SZ     (128*AS_STRIDE)
#define BS_SZ     (32*BS_STRIDE)
#define GEMM_SMEM ((2*AS_SZ + 2*BS_SZ)*4)

template <int MODE>
__global__ __launch_bounds__(256, 2) void gemm_tf32(const float* __restrict__ Bm,
                                                    float* __restrict__ Cout,
                                                    int Kdim, int Ndim) {
    extern __shared__ float sm[];
    float* Bs = sm + 2*AS_SZ;

    const int tid  = threadIdx.x;
    const int lane = tid & 31;
    const int warp = tid >> 5;
    const int wm = (warp >> 2) * 64;
    const int wn = (warp & 3) * 32;
    const int bm = blockIdx.y * 128;
    const int bn = blockIdx.x * 128;

    const uint32_t as_u = (uint32_t)__cvta_generic_to_shared(sm);

    float acc[4][4][4];
#pragma unroll
    for (int mi = 0; mi < 4; mi++)
#pragma unroll
        for (int ni = 0; ni < 4; ni++)
#pragma unroll
            for (int r = 0; r < 4; r++) acc[mi][ni][r] = 0.f;

    const int KT = Kdim / 32;

    auto load_tiles = [&](int buf, int k0) {
        const uint32_t a_base = as_u + (uint32_t)(buf * AS_SZ * 4);
        const uint32_t b_base = as_u + (uint32_t)((2*AS_SZ + buf * BS_SZ) * 4);
#pragma unroll
        for (int i = 0; i < 4; i++) {
            int idx = tid + i * 256;
            int row = idx >> 3;
            int c4  = idx & 7;
            cpa16(a_base + (uint32_t)((row * AS_STRIDE + c4 * 4) * 4),
                  g_Y + (size_t)(bm + row) * Kdim + k0 + c4 * 4);
        }
#pragma unroll
        for (int i = 0; i < 4; i++) {
            int idx = tid + i * 256;
            int row = idx >> 5;
            int c4  = idx & 31;
            cpa16(b_base + (uint32_t)((row * BS_STRIDE + c4 * 4) * 4),
                  Bm + (size_t)(k0 + row) * Ndim + bn + c4 * 4);
        }
        cpa_commit();
    };

    load_tiles(0, 0);

    for (int kt = 0; kt < KT; kt++) {
        const int buf = kt & 1;
        if (kt + 1 < KT) {
            load_tiles(buf ^ 1, (kt + 1) * 32);
            asm volatile("cp.async.wait_group 1;\n");
        } else {
            asm volatile("cp.async.wait_group 0;\n");
        }
        __syncthreads();

        const uint32_t a_base = as_u + (uint32_t)(buf * AS_SZ * 4);
        const float* Bsb = Bs + buf * BS_SZ;

#pragma unroll
        for (int s = 0; s < 4; s++) {
            uint32_t afr[4][4];
#pragma unroll
            for (int mi = 0; mi < 4; mi++) {
                uint32_t addr = a_base +
                    (uint32_t)(((wm + mi * 16 + (lane & 15)) * AS_STRIDE +
                                s * 8 + (lane >> 4) * 4) * 4);
                ldsm_x4(addr, afr[mi][0], afr[mi][1], afr[mi][2], afr[mi][3]);
            }
            uint32_t bfr[4][2];
#pragma unroll
            for (int ni = 0; ni < 4; ni++) {
                int col = wn + ni * 8 + (lane >> 2);
                bfr[ni][0] = f2tf32f(Bsb[(s * 8 + (lane & 3)) * BS_STRIDE + col]);
                bfr[ni][1] = f2tf32f(Bsb[(s * 8 + 4 + (lane & 3)) * BS_STRIDE + col]);
            }
#pragma unroll
            for (int mi = 0; mi < 4; mi++)
#pragma unroll
                for (int ni = 0; ni < 4; ni++)
                    mma_tf32(acc[mi][ni], afr[mi], bfr[ni]);
        }
        __syncthreads();
    }

    const int g  = lane >> 2;
    const int tc = lane & 3;
#pragma unroll
    for (int mi = 0; mi < 4; mi++) {
#pragma unroll
        for (int ni = 0; ni < 4; ni++) {
            int ncol = bn + wn + ni * 8 + 2 * tc;
#pragma unroll
            for (int half = 0; half < 2; half++) {
                int mrow = bm + wm + mi * 16 + g + half * 8;
                float2 v = make_float2(acc[mi][ni][half * 2], acc[mi][ni][half * 2 + 1]);
                if (MODE == 2) {
                    *(float2*)(Cout + (size_t)mrow * Ndim + ncol) = v;
                } else {
                    v.x = roundtf(v.x);   // pre-round for attention's mma consumers
                    v.y = roundtf(v.y);
                    int which = ncol >> 10;
                    int h     = (ncol & 1023) >> 6;
                    int d     = ncol & 63;
                    int b     = mrow >> 11;
                    int t     = mrow & 2047;
                    float* dst = (which == 0) ? g_Q : (which == 1) ? g_K : g_V;
                    *(float2*)(dst + (((size_t)(b * HH + h) * TT + t) * DD) + d) = v;
                }
            }
        }
    }
}

// ---------------------------------------------------------------------------
// Tensor-core flash attention (tf32 mma), BQ=64, BK=64, 4 warps (m16 each).
// Q/K/V pre-rounded tf32: no cvt at load. K in smem as [key][d] (B-frag via
// ldmatrix.x4), V transposed to Vt[d][key] (B-frag via ldmatrix.x4).
// Stride 68 floats -> ldmatrix rows tile all 32 banks, conflict-free.
// ---------------------------------------------------------------------------
__global__ __launch_bounds__(128, 3) void attn_mma() {
    __shared__ float Ks[64][68];
    __shared__ float Vt[64][68];          // Vt[d][key]

    const int tid  = threadIdx.x;
    const int lane = tid & 31;
    const int warp = tid >> 5;                    // 0..3 -> rows warp*16..+15
    const int qt   = (int)(gridDim.x - 1 - blockIdx.x);  // longest first
    const int bh   = blockIdx.y;
    const int g    = lane >> 2;                   // 0..7
    const int tc   = lane & 3;                    // 0..3
    const unsigned FULL = 0xffffffffu;

    const int tq0 = qt * 64 + warp * 16 + g;      // row for c0/c1
    const int tq1 = tq0 + 8;                      // row for c2/c3

    // ldmatrix per-lane base addresses
    const int lane7 = lane & 7;
    const int mq    = lane >> 3;                  // matrix index 0..3 in x4
    const uint32_t ks_u = (uint32_t)__cvta_generic_to_shared(Ks);
    const uint32_t vt_u = (uint32_t)__cvta_generic_to_shared(Vt);
    // K: matrix m covers d-cols (m>>1)*8 + (m&1)*4, rows = keys 8nt+lane7
    const uint32_t kaddr0 = ks_u + (uint32_t)((lane7 * 68 + (mq & 1) * 4 + (mq >> 1) * 8) * 4);
    // V: matrix m covers d-rows 8*(m>>1)+lane7, key-cols (m&1)*4
    const uint32_t vaddr0 = vt_u + (uint32_t)((((mq >> 1) * 8 + lane7) * 68 + (mq & 1) * 4) * 4);

    // Q A-fragments: g_Q pre-rounded; *0.125 is exact -> still tf32
    const float* qb = g_Q + (size_t)bh * TT * DD;
    uint32_t qa[8][4];
#pragma unroll
    for (int s = 0; s < 8; s++) {
        qa[s][0] = __float_as_uint(qb[(size_t)tq0 * DD + 8*s + tc]     * 0.125f);
        qa[s][1] = __float_as_uint(qb[(size_t)tq1 * DD + 8*s + tc]     * 0.125f);
        qa[s][2] = __float_as_uint(qb[(size_t)tq0 * DD + 8*s + tc + 4] * 0.125f);
        qa[s][3] = __float_as_uint(qb[(size_t)tq1 * DD + 8*s + tc + 4] * 0.125f);
    }

    float o[8][4];
#pragma unroll
    for (int od = 0; od < 8; od++)
#pragma unroll
        for (int r = 0; r < 4; r++) o[od][r] = 0.f;
    float m0 = -1e30f, m1 = -1e30f, l0 = 0.f, l1 = 0.f;

    const float* kb = g_K + (size_t)bh * TT * DD;
    const float* vb = g_V + (size_t)bh * TT * DD;

    const int nkt = qt + 1;
    for (int kt = 0; kt < nkt; kt++) {
        // ---- cooperative K/V tile load; V transposed into Vt ----
#pragma unroll
        for (int t = 0; t < 8; t++) {
            int f = tid + t * 128;          // 0..1023
            int r = f >> 4;                 // 0..63 (key)
            int c = (f & 15) * 4;           // 0..60 (dim)
            float4 k4 = *(const float4*)(kb + (size_t)(kt*64 + r) * DD + c);
            float4 v4 = *(const float4*)(vb + (size_t)(kt*64 + r) * DD + c);
            *(float4*)&Ks[r][c] = k4;
            Vt[c+0][r] = v4.x;
            Vt[c+1][r] = v4.y;
            Vt[c+2][r] = v4.z;
            Vt[c+3][r] = v4.w;
        }
        __syncthreads();

        const bool masked = (kt == qt);
        const int kbase = kt * 64;
        const int ntc = masked ? (warp * 2 + 2) : 8;

        // ---- S = Q K^T ----
        float sc[8][4];
        for (int nt = 0; nt < ntc; nt++) {
            float c4[4] = {0.f, 0.f, 0.f, 0.f};
            const uint32_t ka = kaddr0 + (uint32_t)(nt * 2176);  // 8*68*4
#pragma unroll
            for (int s2 = 0; s2 < 4; s2++) {
                uint32_t b0, b1, b2r, b3;
                ldsm_x4(ka + (uint32_t)(s2 * 64), b0, b1, b2r, b3);
                uint32_t lo[2] = {b0, b1};
                uint32_t hi[2] = {b2r, b3};
                mma_tf32(c4, qa[2*s2],     lo);
                mma_tf32(c4, qa[2*s2 + 1], hi);
            }
            if (masked) {
                int k0 = kbase + 8*nt + 2*tc;
                if (k0     > tq0) c4[0] = -1e30f;
                if (k0 + 1 > tq0) c4[1] = -1e30f;
                if (k0     > tq1) c4[2] = -1e30f;
                if (k0 + 1 > tq1) c4[3] = -1e30f;
            }
            sc[nt][0] = c4[0]; sc[nt][1] = c4[1]; sc[nt][2] = c4[2]; sc[nt][3] = c4[3];
        }

        // ---- online softmax ----
        float rm0 = -1e30f, rm1 = -1e30f;
        for (int nt = 0; nt < ntc; nt++) {
            rm0 = fmaxf(rm0, fmaxf(sc[nt][0], sc[nt][1]));
            rm1 = fmaxf(rm1, fmaxf(sc[nt][2], sc[nt][3]));
        }
        rm0 = fmaxf(rm0, __shfl_xor_sync(FULL, rm0, 1));
        rm0 = fmaxf(rm0, __shfl_xor_sync(FULL, rm0, 2));
        rm1 = fmaxf(rm1, __shfl_xor_sync(FULL, rm1, 1));
        rm1 = fmaxf(rm1, __shfl_xor_sync(FULL, rm1, 2));
        const float m0n = fmaxf(m0, rm0);
        const float m1n = fmaxf(m1, rm1);
        const float a0 = __expf(m0 - m0n);
        const float a1 = __expf(m1 - m1n);
        l0 *= a0; l1 *= a1;
#pragma unroll
        for (int od = 0; od < 8; od++) {
            o[od][0] *= a0; o[od][1] *= a0;
            o[od][2] *= a1; o[od][3] *= a1;
        }
        m0 = m0n; m1 = m1n;

        // ---- P = exp(S - m), C-layout -> A-layout via shfl, PV mma ----
        const int src_lo = (lane & ~3) | (tc >> 1);
        const int src_hi = src_lo | 2;
        const bool odd = tc & 1;
        for (int nt = 0; nt < ntc; nt++) {
            float p0 = __expf(sc[nt][0] - m0n);
            float p1 = __expf(sc[nt][1] - m0n);
            float p2 = __expf(sc[nt][2] - m1n);
            float p3 = __expf(sc[nt][3] - m1n);
            l0 += p0 + p1; l1 += p2 + p3;

            float x0 = __shfl_sync(FULL, p0, src_lo);
            float x1 = __shfl_sync(FULL, p1, src_lo);
            float y0 = __shfl_sync(FULL, p0, src_hi);
            float y1 = __shfl_sync(FULL, p1, src_hi);
            float z0 = __shfl_sync(FULL, p2, src_lo);
            float z1 = __shfl_sync(FULL, p3, src_lo);
            float w0 = __shfl_sync(FULL, p2, src_hi);
            float w1 = __shfl_sync(FULL, p3, src_hi);

            uint32_t pa[4];
            pa[0] = f2tf32f(odd ? x1 : x0);   // (row g,   key 8nt+tc)
            pa[1] = f2tf32f(odd ? z1 : z0);   // (row g+8, key 8nt+tc)
            pa[2] = f2tf32f(odd ? y1 : y0);   // (row g,   key 8nt+tc+4)
            pa[3] = f2tf32f(odd ? w1 : w0);   // (row g+8, key 8nt+tc+4)

            const uint32_t va = vaddr0 + (uint32_t)(nt * 32);    // key-col offset
#pragma unroll
            for (int od2 = 0; od2 < 4; od2++) {
                uint32_t b0, b1, b2r, b3;
                ldsm_x4(va + (uint32_t)(od2 * 4352), b0, b1, b2r, b3);  // 16*68*4
                uint32_t lo[2] = {b0, b1};
                uint32_t hi[2] = {b2r, b3};
                mma_tf32(o[2*od2],     pa, lo);
                mma_tf32(o[2*od2 + 1], pa, hi);
            }
        }
        __syncthreads();
    }

    // ---- finalize ----
    l0 += __shfl_xor_sync(FULL, l0, 1);
    l0 += __shfl_xor_sync(FULL, l0, 2);
    l1 += __shfl_xor_sync(FULL, l1, 1);
    l1 += __shfl_xor_sync(FULL, l1, 2);
    const float inv0 = 1.0f / l0;
    const float inv1 = 1.0f / l1;

    const int b = bh >> 4;
    const int h = bh & 15;
    float* y0p = g_Y + ((size_t)(b * TT + tq0)) * CC + h * DD;
    float* y1p = g_Y + ((size_t)(b * TT + tq1)) * CC + h * DD;
#pragma unroll
    for (int od = 0; od < 8; od++) {
        // round for the proj GEMM's tf32 consumers
        *(float2*)(y0p + 8*od + 2*tc) = make_float2(roundtf(o[od][0]*inv0), roundtf(o[od][1]*inv0));
        *(float2*)(y1p + 8*od + 2*tc) = make_float2(roundtf(o[od][2]*inv1), roundtf(o[od][3]*inv1));
    }
}

// ---------------------------------------------------------------------------
// Launch
// ---------------------------------------------------------------------------
extern "C" void kernel_launch(void* const* d_in, const int* in_sizes, int n_in,
                              void* d_out, int out_size) {
    const float* X     = (const float*)d_in[0];   // (B,T,C)
    const float* Wqkv  = (const float*)d_in[1];   // (C,3C)
    const float* Wproj = (const float*)d_in[2];   // (C,C)
    float* out = (float*)d_out;                   // (B,T,C)

    cudaFuncSetAttribute(gemm_tf32<1>, cudaFuncAttributeMaxDynamicSharedMemorySize, GEMM_SMEM);
    cudaFuncSetAttribute(gemm_tf32<2>, cudaFuncAttributeMaxDynamicSharedMemorySize, GEMM_SMEM);

    // 0) Round X -> g_Y (tf32)
    round_inputs<<<4096, 256>>>(X);

    // 1) QKV = g_Y(Xr) @ W_qkv, rounded scatter into Q/K/V
    gemm_tf32<1><<<dim3(NQKV / 128, MM / 128), 256, GEMM_SMEM>>>(Wqkv, nullptr, CC, NQKV);

    // 2) Causal flash attention (tensor cores) -> g_Y (rounded attn out)
    attn_mma<<<dim3(TT / 64, BB * HH), 128>>>();

    // 3) out = g_Y @ W_proj
    gemm_tf32<2><<<dim3(CC / 128, MM / 128), 256, GEMM_SMEM>>>(Wproj, out, CC, CC);
}

// round 16
// speedup vs baseline: 3.4356x; 1.0050x over previous
#include <cuda_runtime.h>
#include <cuda_bf16.h>
#include <cstdint>

// Problem constants
#define BB   2
#define TT   2048
#define CC   1024
#define HH   16
#define DD   64
#define MM   (BB*TT)        // 4096
#define NQKV (3*CC)         // 3072

// Scratch (device globals, 64 MB total — same footprint as the passing R4)
__device__ float g_Q[(size_t)BB*HH*TT*DD];   // [B,H,T,64]  (tf32-rounded)
__device__ float g_K[(size_t)BB*HH*TT*DD];
__device__ float g_V[(size_t)BB*HH*TT*DD];
__device__ float g_Y[(size_t)MM*CC];         // phase 0-1: tf32-rounded X
                                             // phase 2-3: attn out (rounded)

// ---------------------------------------------------------------------------
// PTX helpers
// ---------------------------------------------------------------------------
__device__ __forceinline__ void cpa16(uint32_t saddr, const void* gptr) {
    asm volatile("cp.async.cg.shared.global [%0], [%1], 16;\n" :: "r"(saddr), "l"(gptr));
}
__device__ __forceinline__ void cpa_commit() { asm volatile("cp.async.commit_group;\n"); }

__device__ __forceinline__ uint32_t f2tf32f(float f) {
    uint32_t r;
    asm("cvt.rna.tf32.f32 %0, %1;\n" : "=r"(r) : "f"(f));
    return r;
}
__device__ __forceinline__ float roundtf(float f) {
    return __uint_as_float(f2tf32f(f));
}
__device__ __forceinline__ void ldsm_x4(uint32_t addr, uint32_t& x0, uint32_t& x1,
                                        uint32_t& x2, uint32_t& x3) {
    asm volatile("ldmatrix.sync.aligned.m8n8.x4.shared.b16 {%0,%1,%2,%3}, [%4];\n"
                 : "=r"(x0), "=r"(x1), "=r"(x2), "=r"(x3) : "r"(addr));
}
__device__ __forceinline__ void mma_tf32(float* c, const uint32_t* a, const uint32_t* b) {
    asm volatile(
        "mma.sync.aligned.m16n8k8.row.col.f32.tf32.tf32.f32 "
        "{%0,%1,%2,%3}, {%4,%5,%6,%7}, {%8,%9}, {%0,%1,%2,%3};\n"
        : "+f"(c[0]), "+f"(c[1]), "+f"(c[2]), "+f"(c[3])
        : "r"(a[0]), "r"(a[1]), "r"(a[2]), "r"(a[3]), "r"(b[0]), "r"(b[1]));
}

// ---------------------------------------------------------------------------
// Pre-round X to tf32 into g_Y (GEMM-1 reads it; attention later overwrites).
// 4096 blocks x 256 threads, 1 float4 each.
// ---------------------------------------------------------------------------
__global__ __launch_bounds__(256) void round_inputs(const float* __restrict__ X) {
    size_t idx = (size_t)blockIdx.x * 256 + threadIdx.x;
    float4 v = ((const float4*)X)[idx];
    v.x = roundtf(v.x); v.y = roundtf(v.y); v.z = roundtf(v.z); v.w = roundtf(v.w);
    ((float4*)g_Y)[idx] = v;
}

// ---------------------------------------------------------------------------
// tf32 tensor-core GEMM: C[M,N] = g_Y[M,K] @ B[K,N]
// A (g_Y) is pre-rounded -> no A-side cvt. B fragments cvt'd at load (32/ktile).
// BM=128, BN=128, BK=32, 256 thr, 8 warps.
// MODE 1: B=W_qkv -> rounded scatter into g_Q/g_K/g_V
// MODE 2: B=W_proj -> raw fp32 store to Cout
// ---------------------------------------------------------------------------
#define AS_STRIDE 36
#define BS_STRIDE 136
#define AS_SZ     (128*AS_STRIDE)
#define BS_SZ     (32*BS_STRIDE)
#define GEMM_SMEM ((2*AS_SZ + 2*BS_SZ)*4)

template <int MODE>
__global__ __launch_bounds__(256, 2) void gemm_tf32(const float* __restrict__ Bm,
                                                    float* __restrict__ Cout,
                                                    int Kdim, int Ndim) {
    extern __shared__ float sm[];
    float* Bs = sm + 2*AS_SZ;

    const int tid  = threadIdx.x;
    const int lane = tid & 31;
    const int warp = tid >> 5;
    const int wm = (warp >> 2) * 64;
    const int wn = (warp & 3) * 32;
    const int bm = blockIdx.y * 128;
    const int bn = blockIdx.x * 128;

    const uint32_t as_u = (uint32_t)__cvta_generic_to_shared(sm);

    float acc[4][4][4];
#pragma unroll
    for (int mi = 0; mi < 4; mi++)
#pragma unroll
        for (int ni = 0; ni < 4; ni++)
#pragma unroll
            for (int r = 0; r < 4; r++) acc[mi][ni][r] = 0.f;

    const int KT = Kdim / 32;

    auto load_tiles = [&](int buf, int k0) {
        const uint32_t a_base = as_u + (uint32_t)(buf * AS_SZ * 4);
        const uint32_t b_base = as_u + (uint32_t)((2*AS_SZ + buf * BS_SZ) * 4);
#pragma unroll
        for (int i = 0; i < 4; i++) {
            int idx = tid + i * 256;
            int row = idx >> 3;
            int c4  = idx & 7;
            cpa16(a_base + (uint32_t)((row * AS_STRIDE + c4 * 4) * 4),
                  g_Y + (size_t)(bm + row) * Kdim + k0 + c4 * 4);
        }
#pragma unroll
        for (int i = 0; i < 4; i++) {
            int idx = tid + i * 256;
            int row = idx >> 5;
            int c4  = idx & 31;
            cpa16(b_base + (uint32_t)((row * BS_STRIDE + c4 * 4) * 4),
                  Bm + (size_t)(k0 + row) * Ndim + bn + c4 * 4);
        }
        cpa_commit();
    };

    load_tiles(0, 0);

    for (int kt = 0; kt < KT; kt++) {
        const int buf = kt & 1;
        if (kt + 1 < KT) {
            load_tiles(buf ^ 1, (kt + 1) * 32);
            asm volatile("cp.async.wait_group 1;\n");
        } else {
            asm volatile("cp.async.wait_group 0;\n");
        }
        __syncthreads();

        const uint32_t a_base = as_u + (uint32_t)(buf * AS_SZ * 4);
        const float* Bsb = Bs + buf * BS_SZ;

#pragma unroll
        for (int s = 0; s < 4; s++) {
            uint32_t afr[4][4];
#pragma unroll
            for (int mi = 0; mi < 4; mi++) {
                uint32_t addr = a_base +
                    (uint32_t)(((wm + mi * 16 + (lane & 15)) * AS_STRIDE +
                                s * 8 + (lane >> 4) * 4) * 4);
                ldsm_x4(addr, afr[mi][0], afr[mi][1], afr[mi][2], afr[mi][3]);
            }
            uint32_t bfr[4][2];
#pragma unroll
            for (int ni = 0; ni < 4; ni++) {
                int col = wn + ni * 8 + (lane >> 2);
                bfr[ni][0] = f2tf32f(Bsb[(s * 8 + (lane & 3)) * BS_STRIDE + col]);
                bfr[ni][1] = f2tf32f(Bsb[(s * 8 + 4 + (lane & 3)) * BS_STRIDE + col]);
            }
#pragma unroll
            for (int mi = 0; mi < 4; mi++)
#pragma unroll
                for (int ni = 0; ni < 4; ni++)
                    mma_tf32(acc[mi][ni], afr[mi], bfr[ni]);
        }
        __syncthreads();
    }

    const int g  = lane >> 2;
    const int tc = lane & 3;
#pragma unroll
    for (int mi = 0; mi < 4; mi++) {
#pragma unroll
        for (int ni = 0; ni < 4; ni++) {
            int ncol = bn + wn + ni * 8 + 2 * tc;
#pragma unroll
            for (int half = 0; half < 2; half++) {
                int mrow = bm + wm + mi * 16 + g + half * 8;
                float2 v = make_float2(acc[mi][ni][half * 2], acc[mi][ni][half * 2 + 1]);
                if (MODE == 2) {
                    *(float2*)(Cout + (size_t)mrow * Ndim + ncol) = v;
                } else {
                    v.x = roundtf(v.x);   // pre-round for attention's mma consumers
                    v.y = roundtf(v.y);
                    int which = ncol >> 10;
                    int h     = (ncol & 1023) >> 6;
                    int d     = ncol & 63;
                    int b     = mrow >> 11;
                    int t     = mrow & 2047;
                    float* dst = (which == 0) ? g_Q : (which == 1) ? g_K : g_V;
                    *(float2*)(dst + (((size_t)(b * HH + h) * TT + t) * DD) + d) = v;
                }
            }
        }
    }
}

// ---------------------------------------------------------------------------
// Tensor-core flash attention (tf32 mma), BQ=64, BK=64, 4 warps (m16 each).
// Q/K/V pre-rounded tf32: no cvt at load. K in smem as [key][d] (B-frag via
// ldmatrix.x4), V transposed to Vt[d][key] (B-frag via ldmatrix.x4).
// Stride 68 floats -> ldmatrix rows tile all 32 banks, conflict-free.
// ---------------------------------------------------------------------------
__global__ __launch_bounds__(128, 3) void attn_mma() {
    __shared__ float Ks[64][68];
    __shared__ float Vt[64][68];          // Vt[d][key]

    const int tid  = threadIdx.x;
    const int lane = tid & 31;
    const int warp = tid >> 5;                    // 0..3 -> rows warp*16..+15
    const int qt   = (int)(gridDim.x - 1 - blockIdx.x);  // longest first
    const int bh   = blockIdx.y;
    const int g    = lane >> 2;                   // 0..7
    const int tc   = lane & 3;                    // 0..3
    const unsigned FULL = 0xffffffffu;

    const int tq0 = qt * 64 + warp * 16 + g;      // row for c0/c1
    const int tq1 = tq0 + 8;                      // row for c2/c3

    // ldmatrix per-lane base addresses
    const int lane7 = lane & 7;
    const int mq    = lane >> 3;                  // matrix index 0..3 in x4
    const uint32_t ks_u = (uint32_t)__cvta_generic_to_shared(Ks);
    const uint32_t vt_u = (uint32_t)__cvta_generic_to_shared(Vt);
    // K: matrix m covers d-cols (m>>1)*8 + (m&1)*4, rows = keys 8nt+lane7
    const uint32_t kaddr0 = ks_u + (uint32_t)((lane7 * 68 + (mq & 1) * 4 + (mq >> 1) * 8) * 4);
    // V: matrix m covers d-rows 8*(m>>1)+lane7, key-cols (m&1)*4
    const uint32_t vaddr0 = vt_u + (uint32_t)((((mq >> 1) * 8 + lane7) * 68 + (mq & 1) * 4) * 4);

    // Q A-fragments: g_Q pre-rounded; *0.125 is exact -> still tf32
    const float* qb = g_Q + (size_t)bh * TT * DD;
    uint32_t qa[8][4];
#pragma unroll
    for (int s = 0; s < 8; s++) {
        qa[s][0] = __float_as_uint(qb[(size_t)tq0 * DD + 8*s + tc]     * 0.125f);
        qa[s][1] = __float_as_uint(qb[(size_t)tq1 * DD + 8*s + tc]     * 0.125f);
        qa[s][2] = __float_as_uint(qb[(size_t)tq0 * DD + 8*s + tc + 4] * 0.125f);
        qa[s][3] = __float_as_uint(qb[(size_t)tq1 * DD + 8*s + tc + 4] * 0.125f);
    }

    float o[8][4];
#pragma unroll
    for (int od = 0; od < 8; od++)
#pragma unroll
        for (int r = 0; r < 4; r++) o[od][r] = 0.f;
    float m0 = -1e30f, m1 = -1e30f, l0 = 0.f, l1 = 0.f;

    const float* kb = g_K + (size_t)bh * TT * DD;
    const float* vb = g_V + (size_t)bh * TT * DD;

    const int nkt = qt + 1;
    for (int kt = 0; kt < nkt; kt++) {
        // ---- cooperative K/V tile load; V transposed into Vt ----
#pragma unroll
        for (int t = 0; t < 8; t++) {
            int f = tid + t * 128;          // 0..1023
            int r = f >> 4;                 // 0..63 (key)
            int c = (f & 15) * 4;           // 0..60 (dim)
            float4 k4 = *(const float4*)(kb + (size_t)(kt*64 + r) * DD + c);
            float4 v4 = *(const float4*)(vb + (size_t)(kt*64 + r) * DD + c);
            *(float4*)&Ks[r][c] = k4;
            Vt[c+0][r] = v4.x;
            Vt[c+1][r] = v4.y;
            Vt[c+2][r] = v4.z;
            Vt[c+3][r] = v4.w;
        }
        __syncthreads();

        const bool masked = (kt == qt);
        const int kbase = kt * 64;
        const int ntc = masked ? (warp * 2 + 2) : 8;

        // ---- S = Q K^T ----
        float sc[8][4];
        for (int nt = 0; nt < ntc; nt++) {
            float c4[4] = {0.f, 0.f, 0.f, 0.f};
            const uint32_t ka = kaddr0 + (uint32_t)(nt * 2176);  // 8*68*4
#pragma unroll
            for (int s2 = 0; s2 < 4; s2++) {
                uint32_t b0, b1, b2r, b3;
                ldsm_x4(ka + (uint32_t)(s2 * 64), b0, b1, b2r, b3);
                uint32_t lo[2] = {b0, b1};
                uint32_t hi[2] = {b2r, b3};
                mma_tf32(c4, qa[2*s2],     lo);
                mma_tf32(c4, qa[2*s2 + 1], hi);
            }
            if (masked) {
                int k0 = kbase + 8*nt + 2*tc;
                if (k0     > tq0) c4[0] = -1e30f;
                if (k0 + 1 > tq0) c4[1] = -1e30f;
                if (k0     > tq1) c4[2] = -1e30f;
                if (k0 + 1 > tq1) c4[3] = -1e30f;
            }
            sc[nt][0] = c4[0]; sc[nt][1] = c4[1]; sc[nt][2] = c4[2]; sc[nt][3] = c4[3];
        }

        // ---- online softmax ----
        float rm0 = -1e30f, rm1 = -1e30f;
        for (int nt = 0; nt < ntc; nt++) {
            rm0 = fmaxf(rm0, fmaxf(sc[nt][0], sc[nt][1]));
            rm1 = fmaxf(rm1, fmaxf(sc[nt][2], sc[nt][3]));
        }
        rm0 = fmaxf(rm0, __shfl_xor_sync(FULL, rm0, 1));
        rm0 = fmaxf(rm0, __shfl_xor_sync(FULL, rm0, 2));
        rm1 = fmaxf(rm1, __shfl_xor_sync(FULL, rm1, 1));
        rm1 = fmaxf(rm1, __shfl_xor_sync(FULL, rm1, 2));
        const float m0n = fmaxf(m0, rm0);
        const float m1n = fmaxf(m1, rm1);
        const float a0 = __expf(m0 - m0n);
        const float a1 = __expf(m1 - m1n);
        l0 *= a0; l1 *= a1;
#pragma unroll
        for (int od = 0; od < 8; od++) {
            o[od][0] *= a0; o[od][1] *= a0;
            o[od][2] *= a1; o[od][3] *= a1;
        }
        m0 = m0n; m1 = m1n;

        // ---- P = exp(S - m), C-layout -> A-layout via shfl, PV mma ----
        const int src_lo = (lane & ~3) | (tc >> 1);
        const int src_hi = src_lo | 2;
        const bool odd = tc & 1;
        for (int nt = 0; nt < ntc; nt++) {
            float p0 = __expf(sc[nt][0] - m0n);
            float p1 = __expf(sc[nt][1] - m0n);
            float p2 = __expf(sc[nt][2] - m1n);
            float p3 = __expf(sc[nt][3] - m1n);
            l0 += p0 + p1; l1 += p2 + p3;

            float x0 = __shfl_sync(FULL, p0, src_lo);
            float x1 = __shfl_sync(FULL, p1, src_lo);
            float y0 = __shfl_sync(FULL, p0, src_hi);
            float y1 = __shfl_sync(FULL, p1, src_hi);
            float z0 = __shfl_sync(FULL, p2, src_lo);
            float z1 = __shfl_sync(FULL, p3, src_lo);
            float w0 = __shfl_sync(FULL, p2, src_hi);
            float w1 = __shfl_sync(FULL, p3, src_hi);

            uint32_t pa[4];
            pa[0] = f2tf32f(odd ? x1 : x0);   // (row g,   key 8nt+tc)
            pa[1] = f2tf32f(odd ? z1 : z0);   // (row g+8, key 8nt+tc)
            pa[2] = f2tf32f(odd ? y1 : y0);   // (row g,   key 8nt+tc+4)
            pa[3] = f2tf32f(odd ? w1 : w0);   // (row g+8, key 8nt+tc+4)

            const uint32_t va = vaddr0 + (uint32_t)(nt * 32);    // key-col offset
#pragma unroll
            for (int od2 = 0; od2 < 4; od2++) {
                uint32_t b0, b1, b2r, b3;
                ldsm_x4(va + (uint32_t)(od2 * 4352), b0, b1, b2r, b3);  // 16*68*4
                uint32_t lo[2] = {b0, b1};
                uint32_t hi[2] = {b2r, b3};
                mma_tf32(o[2*od2],     pa, lo);
                mma_tf32(o[2*od2 + 1], pa, hi);
            }
        }
        __syncthreads();
    }

    // ---- finalize ----
    l0 += __shfl_xor_sync(FULL, l0, 1);
    l0 += __shfl_xor_sync(FULL, l0, 2);
    l1 += __shfl_xor_sync(FULL, l1, 1);
    l1 += __shfl_xor_sync(FULL, l1, 2);
    const float inv0 = 1.0f / l0;
    const float inv1 = 1.0f / l1;

    const int b = bh >> 4;
    const int h = bh & 15;
    float* y0p = g_Y + ((size_t)(b * TT + tq0)) * CC + h * DD;
    float* y1p = g_Y + ((size_t)(b * TT + tq1)) * CC + h * DD;
#pragma unroll
    for (int od = 0; od < 8; od++) {
        // round for the proj GEMM's tf32 consumers
        *(float2*)(y0p + 8*od + 2*tc) = make_float2(roundtf(o[od][0]*inv0), roundtf(o[od][1]*inv0));
        *(float2*)(y1p + 8*od + 2*tc) = make_float2(roundtf(o[od][2]*inv1), roundtf(o[od][3]*inv1));
    }
}

// ---------------------------------------------------------------------------
// Launch
// ---------------------------------------------------------------------------
extern "C" void kernel_launch(void* const* d_in, const int* in_sizes, int n_in,
                              void* d_out, int out_size) {
    const float* X     = (const float*)d_in[0];   // (B,T,C)
    const float* Wqkv  = (const float*)d_in[1];   // (C,3C)
    const float* Wproj = (const float*)d_in[2];   // (C,C)
    float* out = (float*)d_out;                   // (B,T,C)

    cudaFuncSetAttribute(gemm_tf32<1>, cudaFuncAttributeMaxDynamicSharedMemorySize, GEMM_SMEM);
    cudaFuncSetAttribute(gemm_tf32<2>, cudaFuncAttributeMaxDynamicSharedMemorySize, GEMM_SMEM);

    // 0) Round X -> g_Y (tf32)
    round_inputs<<<4096, 256>>>(X);

    // 1) QKV = g_Y(Xr) @ W_qkv, rounded scatter into Q/K/V
    gemm_tf32<1><<<dim3(NQKV / 128, MM / 128), 256, GEMM_SMEM>>>(Wqkv, nullptr, CC, NQKV);

    // 2) Causal flash attention (tensor cores) -> g_Y (rounded attn out)
    attn_mma<<<dim3(TT / 64, BB * HH), 128>>>();

    // 3) out = g_Y @ W_proj
    gemm_tf32<2><<<dim3(CC / 128, MM / 128), 256, GEMM_SMEM>>>(Wproj, out, CC, CC);
}